// round 14
// baseline (speedup 1.0000x reference)
#include <cuda_runtime.h>
#include <math.h>

#define HH 496
#define WW 496
#define HW (HH * WW)
#define BDIM 4
#define NTOT (BDIM * HW)
#define TPB 256
#define BLK_PER_B (HW / TPB)         // 961
#define NBLK (BDIM * BLK_PER_B)      // 3844 tiles of 256 elements
#define GRID_P (148 * 6)             // 888 persistent blocks, 6/SM
#define NW (TPB / 32)

__device__ float g_num = 0.0f;
__device__ int g_cnt = 0;
__device__ unsigned int g_done = 0;

__global__ void __launch_bounds__(TPB, 6) iou_k(const float* __restrict__ iou_pred,
                                                const int* __restrict__ mask,
                                                const float* __restrict__ box_pred,
                                                const float* __restrict__ box_gt,
                                                float* __restrict__ out) {
    __shared__ float s_red[NW];
    __shared__ int s_cnt[NW];

    const int tid = threadIdx.x;
    const int lane = tid & 31;
    const int w = tid >> 5;

    float lnum = 0.0f;
    int lcnt = 0;

    int tile = blockIdx.x;

    // ---- prefetch slot: box_gt (worst-latency AoS gather) + mask + iou_pred ----
    float qb0, qb1, qb2, qb3, qb4, qb5, qb6, qip;
    int qm;
    {
        const int n = tile * TPB + tid;
        const float* bg = box_gt + (size_t)n * 7;
        qb0 = __ldg(bg);     qb1 = __ldg(bg + 1); qb2 = __ldg(bg + 2);
        qb3 = __ldg(bg + 3); qb4 = __ldg(bg + 4); qb5 = __ldg(bg + 5);
        qb6 = __ldg(bg + 6);
        qm = __ldg(mask + n);
        qip = __ldg(iou_pred + n);
    }

    while (tile < NBLK) {
        const int ntile = tile + GRID_P;

        // Current-tile values move out of the prefetch slot.
        const float pb0 = qb0, pb1 = qb1, pb2 = qb2, pb3 = qb3;
        const float pb4 = qb4, pb5 = qb5, pb6 = qb6, ip = qip;
        const int m = qm;

        // ---- issue NEXT tile's expensive loads first (hidden behind compute) ----
        {
            const int pt = (ntile < NBLK) ? ntile : tile;
            const int pn = pt * TPB + tid;
            const float* bg = box_gt + (size_t)pn * 7;
            qb0 = __ldg(bg);     qb1 = __ldg(bg + 1); qb2 = __ldg(bg + 2);
            qb3 = __ldg(bg + 3); qb4 = __ldg(bg + 4); qb5 = __ldg(bg + 5);
            qb6 = __ldg(bg + 6);
            qm = __ldg(mask + pn);
            qip = __ldg(iou_pred + pn);
        }

        // ---- in-phase coalesced box_pred loads (cheap: 1 wavefront each) ----
        const int b = tile / BLK_PER_B;
        const int hw = tile * TPB + tid - b * HW;
        const float* bp = box_pred + (size_t)b * 7 * HW + hw;   // [B,7,H,W]
        const float pa0 = __ldg(bp);
        const float pa1 = __ldg(bp + HW);
        const float pa2 = __ldg(bp + 2 * HW);
        const float pa3 = __ldg(bp + 3 * HW);
        const float pa4 = __ldg(bp + 4 * HW);
        const float pa5 = __ldg(bp + 5 * HW);
        const float pa6 = __ldg(bp + 6 * HW);

        const unsigned int ball = __ballot_sync(0xffffffffu, m != 0);

        // ---- geometry (R11 math, unchanged) ----
        const float s = fmaf(pa3 * pa4, pa5, fmaf(pb3 * pb4, pb5, 1e-7f));
        const float zo = fmaxf(fminf(pa2 + 0.5f * pa5, pb2 + 0.5f * pb5) -
                               fmaxf(pa2 - 0.5f * pa5, pb2 - 0.5f * pb5), 0.0f);

        float sa, ca, sr, cr;
        __sincosf(pa6, &sa, &ca);
        __sincosf(pb6 - pa6, &sr, &cr);

        const float tx = pb0 - pa0, ty = pb1 - pa1;
        const float rx = fmaf(ca, tx, sa * ty);
        const float ry = fmaf(ca, ty, -sa * tx);

        const float hx = 0.5f * pa3, hy = 0.5f * pa4;
        const float lx = 0.5f * pb3, ly = 0.5f * pb4;

        const float crlx = cr * lx, srlx = sr * lx;
        const float crly = cr * ly, srly = sr * ly;
        const float c0x = rx + crlx - srly, c0y = ry + srlx + crly;
        const float c1x = rx - crlx - srly, c1y = ry - srlx + crly;

        const float ex0 = -2.0f * crlx, ey0 = -2.0f * srlx;
        const float ex1 =  2.0f * srly, ey1 = -2.0f * crly;

        const float rex0 = __fdividef(1.0f, ex0);
        const float rey0 = __fdividef(1.0f, ey0);
        const float rex1 = __fdividef(1.0f, ex1);
        const float rey1 = __fdividef(1.0f, ey1);

        const float k0 = fmaf(ey0, c0x, -ex0 * c0y);
        const float k1 = fmaf(ey1, c1x, -ex1 * c1y);
        const float k2 = k0 - 2.0f * fmaf(ey0, rx, -ex0 * ry);
        const float k3 = k1 - 2.0f * fmaf(ey1, rx, -ex1 * ry);

        float acc = 0.0f;

        // Pass B: B edges vs A AABB (branchless slab test).
        {
            auto slabB = [&](float cx, float cy, float rex, float rey, float k) {
                float tx1 = (-hx - cx) * rex, tx2 = (hx - cx) * rex;
                float ty1 = (-hy - cy) * rey, ty2 = (hy - cy) * rey;
                float t0 = fmaxf(fmaxf(fminf(tx1, tx2), fminf(ty1, ty2)), 0.0f);
                float t1 = fminf(fminf(fmaxf(tx1, tx2), fmaxf(ty1, ty2)), 1.0f);
                acc = fmaf(fmaxf(t1 - t0, 0.0f), k, acc);
            };
            slabB(c0x, c0y,  rex0,  rey0, k0);
            slabB(c1x, c1y,  rex1,  rey1, k1);
            slabB(2.0f * rx - c0x, 2.0f * ry - c0y, -rex0, -rey0, k2);
            slabB(2.0f * rx - c1x, 2.0f * ry - c1y, -rex1, -rey1, k3);
        }

        // Pass A: A edges vs B rect (strip pairs {0,2},{1,3}, branchless).
        {
            const float rhx2 = __fdividef(1.0f, hx + hx);
            const float rhy2 = __fdividef(1.0f, hy + hy);
            const float w0 = rhx2 * rey0, w1 = rhx2 * rey1;
            const float v0 = rhy2 * rex0, v1 = rhy2 * rex1;

            const float exhy0 = ex0 * hy, eyhx0 = ey0 * hx;
            const float exhy1 = ex1 * hy, eyhx1 = ey1 * hx;
            const float kp0 = k0 + exhy0, km0 = k0 - exhy0;
            const float kp1 = k1 + exhy1, km1 = k1 - exhy1;
            const float kp2 = k2 - exhy0, km2 = k2 + exhy0;
            const float kp3 = k3 - exhy1, km3 = k3 + exhy1;

            auto edgeA = [&](float ta0, float tb0, float ta1, float tb1) -> float {
                float t0 = fmaxf(fmaxf(fminf(ta0, tb0), fminf(ta1, tb1)), 0.0f);
                float t1 = fminf(fminf(fmaxf(ta0, tb0), fmaxf(ta1, tb1)), 1.0f);
                return fmaxf(t1 - t0, 0.0f);
            };

            float dts = edgeA(-(kp0 - eyhx0) * w0, (kp2 + eyhx0) * w0,
                              -(kp1 - eyhx1) * w1, (kp3 + eyhx1) * w1);
            dts += edgeA((kp0 + eyhx0) * v0, -(kp2 - eyhx0) * v0,
                         (kp1 + eyhx1) * v1, -(kp3 - eyhx1) * v1);
            dts += edgeA((km0 + eyhx0) * w0, -(km2 - eyhx0) * w0,
                         (km1 + eyhx1) * w1, -(km3 - eyhx1) * w1);
            dts += edgeA(-(km0 - eyhx0) * v0, (km2 + eyhx0) * v0,
                         -(km1 - eyhx1) * v1, (km3 + eyhx1) * v1);

            acc = fmaf(dts, 2.0f * hx * hy, acc);
        }

        const float inter_vol = 0.5f * fabsf(acc) * zo;
        const float iou = __fdividef(inter_vol, s - inter_vol);
        if ((ball >> lane) & 1u) lnum += fabsf(ip - (2.0f * iou - 1.0f));
        lcnt += __popc(ball);

        tile = ntile;
    }

    // ---- block reduction of per-thread accumulators ----
#pragma unroll
    for (int off = 16; off > 0; off >>= 1)
        lnum += __shfl_down_sync(0xffffffffu, lnum, off);
    if (lane == 0) { s_red[w] = lnum; s_cnt[w] = lcnt; }
    __syncthreads();
    if (w == 0) {
        lnum = (lane < NW) ? s_red[lane] : 0.0f;
        lcnt = (lane < NW) ? s_cnt[lane] : 0;
#pragma unroll
        for (int off = NW / 2; off > 0; off >>= 1) {
            lnum += __shfl_down_sync(0xffffffffu, lnum, off);
            lcnt += __shfl_down_sync(0xffffffffu, lcnt, off);
        }
        // ---- last-block finalize (threadfence reduction pattern) ----
        if (lane == 0) {
            atomicAdd(&g_num, lnum);
            atomicAdd(&g_cnt, lcnt);
            __threadfence();
            unsigned int old = atomicAdd(&g_done, 1u);
            if (old == GRID_P - 1) {
                __threadfence();
                float num = *((volatile float*)&g_num);
                int cnt = *((volatile int*)&g_cnt);
                out[0] = num / ((float)cnt + 1e-4f);
                g_num = 0.0f;       // reset for next graph replay
                g_cnt = 0;
                g_done = 0u;
            }
        }
    }
}

extern "C" void kernel_launch(void* const* d_in, const int* in_sizes, int n_in,
                              void* d_out, int out_size) {
    const float* iou_pred = (const float*)d_in[0];
    const int* mask = (const int*)d_in[1];
    // d_in[2] = ind (unused)
    const float* box_pred = (const float*)d_in[3];
    const float* box_gt = (const float*)d_in[4];
    float* out = (float*)d_out;

    iou_k<<<GRID_P, TPB>>>(iou_pred, mask, box_pred, box_gt, out);
}

// round 15
// speedup vs baseline: 1.2600x; 1.2600x over previous
#include <cuda_runtime.h>
#include <math.h>

#define HH 496
#define WW 496
#define HW (HH * WW)
#define BDIM 4
#define NTOT (BDIM * HW)
#define TPB 256
#define BLK_PER_B (HW / TPB)         // 246016/256 = 961 exactly
#define NBLK (BDIM * BLK_PER_B)      // 3844
#define NW (TPB / 32)

__device__ float g_num = 0.0f;
__device__ int g_cnt = 0;
__device__ unsigned int g_done = 0;

__global__ void __launch_bounds__(TPB, 8) iou_k(const float* __restrict__ iou_pred,
                                                const int* __restrict__ mask,
                                                const float* __restrict__ box_pred,
                                                const float* __restrict__ box_gt,
                                                float* __restrict__ out) {
    __shared__ float s_red[NW];
    __shared__ int s_cnt[NW];

    const int tid = threadIdx.x;
    const int lane = tid & 31;
    const int w = tid >> 5;
    const int b = blockIdx.x / BLK_PER_B;
    const int n = blockIdx.x * TPB + tid;
    const int hw = n - b * HW;

    // ---- issue all loads up front: no barriers, maximal MLP ----
    const int m = __ldg(mask + n);
    const float ip = __ldg(iou_pred + n);

    const float* bp = box_pred + (size_t)b * 7 * HW + hw;   // [B,7,H,W] (coalesced)
    const float pa0 = __ldg(bp);
    const float pa1 = __ldg(bp + HW);
    const float pa2 = __ldg(bp + 2 * HW);
    const float pa3 = __ldg(bp + 3 * HW);
    const float pa4 = __ldg(bp + 4 * HW);
    const float pa5 = __ldg(bp + 5 * HW);
    const float pa6 = __ldg(bp + 6 * HW);

    const float* bg = box_gt + (size_t)n * 7;               // [B,H,W,7]
    const float pb0 = __ldg(bg);
    const float pb1 = __ldg(bg + 1);
    const float pb2 = __ldg(bg + 2);
    const float pb3 = __ldg(bg + 3);
    const float pb4 = __ldg(bg + 4);
    const float pb5 = __ldg(bg + 5);
    const float pb6 = __ldg(bg + 6);

    // Predicate now; 'm' dies immediately.
    const unsigned int ball = __ballot_sync(0xffffffffu, m != 0);
    const bool act = (ball >> lane) & 1u;

    // Fold z/volume terms immediately; keep only two live scalars (s, zo).
    const float s = fmaf(pa3 * pa4, pa5, fmaf(pb3 * pb4, pb5, 1e-7f)); // vol_a+vol_b+eps
    const float zo = fmaxf(fminf(pa2 + 0.5f * pa5, pb2 + 0.5f * pb5) -
                           fmaxf(pa2 - 0.5f * pa5, pb2 - 0.5f * pb5), 0.0f);

    // MUFU chains early.
    float sa, ca, sr, cr;
    __sincosf(pa6, &sa, &ca);
    __sincosf(pb6 - pa6, &sr, &cr);

    // Box A's frame: rotate world by -heading_a, center at A. A is the AABB
    // [-hx,hx] x [-hy,hy]; B is a rotated rect centered (rx,ry).
    const float tx = pb0 - pa0, ty = pb1 - pa1;
    const float rx = fmaf(ca, tx, sa * ty);
    const float ry = fmaf(ca, ty, -sa * tx);

    const float hx = 0.5f * pa3, hy = 0.5f * pa4;
    const float lx = 0.5f * pb3, ly = 0.5f * pb4;

    // B corners CCW (c2 = 2T - c0, c3 = 2T - c1; c2/c3 not materialized).
    const float crlx = cr * lx, srlx = sr * lx;
    const float crly = cr * ly, srly = sr * ly;
    const float c0x = rx + crlx - srly, c0y = ry + srlx + crly;
    const float c1x = rx - crlx - srly, c1y = ry - srlx + crly;

    // Edge vectors: e0 = c1-c0, e1 = c2-c1; e2 = -e0, e3 = -e1.
    const float ex0 = -2.0f * crlx, ey0 = -2.0f * srlx;
    const float ex1 =  2.0f * srly, ey1 = -2.0f * crly;

    // Per-edge reciprocals (shared by both passes).
    const float rex0 = __fdividef(1.0f, ex0);
    const float rey0 = __fdividef(1.0f, ey0);
    const float rex1 = __fdividef(1.0f, ex1);
    const float rey1 = __fdividef(1.0f, ey1);

    // Shoelace cross per B edge: k_j = ey_j*c_jx - ex_j*c_jy.
    const float k0 = fmaf(ey0, c0x, -ex0 * c0y);
    const float k1 = fmaf(ey1, c1x, -ex1 * c1y);
    const float k2 = k0 - 2.0f * fmaf(ey0, rx, -ex0 * ry);
    const float k3 = k1 - 2.0f * fmaf(ey1, rx, -ex1 * ry);

    float acc = 0.0f;

    // ---- Pass B: B edges vs A AABB (branchless slab test) ----
    {
        auto slabB = [&](float cx, float cy, float rex, float rey, float k) {
            float tx1 = (-hx - cx) * rex, tx2 = (hx - cx) * rex;
            float ty1 = (-hy - cy) * rey, ty2 = (hy - cy) * rey;
            float t0 = fmaxf(fmaxf(fminf(tx1, tx2), fminf(ty1, ty2)), 0.0f);
            float t1 = fminf(fminf(fmaxf(tx1, tx2), fmaxf(ty1, ty2)), 1.0f);
            acc = fmaf(fmaxf(t1 - t0, 0.0f), k, acc);
        };
        slabB(c0x, c0y,  rex0,  rey0, k0);
        slabB(c1x, c1y,  rex1,  rey1, k1);
        slabB(2.0f * rx - c0x, 2.0f * ry - c0y, -rex0, -rey0, k2);
        slabB(2.0f * rx - c1x, 2.0f * ry - c1y, -rex1, -rey1, k3);
    }

    // ---- Pass A: A edges vs B rect (strip pairs {0,2},{1,3}, branchless) ----
    {
        const float rhx2 = __fdividef(1.0f, hx + hx);
        const float rhy2 = __fdividef(1.0f, hy + hy);
        const float w0 = rhx2 * rey0, w1 = rhx2 * rey1;   // 1/(2 hx ey_j)
        const float v0 = rhy2 * rex0, v1 = rhy2 * rex1;   // 1/(2 hy ex_j)

        // D_j at A corners: D_j(+-hx, +-hy) = k_j + ex_j*(+-hy) - ey_j*(+-hx).
        const float exhy0 = ex0 * hy, eyhx0 = ey0 * hx;
        const float exhy1 = ex1 * hy, eyhx1 = ey1 * hx;
        const float kp0 = k0 + exhy0, km0 = k0 - exhy0;
        const float kp1 = k1 + exhy1, km1 = k1 - exhy1;
        const float kp2 = k2 - exhy0, km2 = k2 + exhy0;   // ex2 = -ex0
        const float kp3 = k3 - exhy1, km3 = k3 + exhy1;

        auto edgeA = [&](float ta0, float tb0, float ta1, float tb1) -> float {
            float t0 = fmaxf(fmaxf(fminf(ta0, tb0), fminf(ta1, tb1)), 0.0f);
            float t1 = fminf(fminf(fmaxf(ta0, tb0), fmaxf(ta1, tb1)), 1.0f);
            return fmaxf(t1 - t0, 0.0f);
        };

        // Top:    V=(+hx,+hy), d=(-2hx,0):  1/s_j = +w_j
        float dts = edgeA(-(kp0 - eyhx0) * w0, (kp2 + eyhx0) * w0,
                          -(kp1 - eyhx1) * w1, (kp3 + eyhx1) * w1);
        // Left:   V=(-hx,+hy), d=(0,-2hy):  1/s_j = -v_j
        dts += edgeA((kp0 + eyhx0) * v0, -(kp2 - eyhx0) * v0,
                     (kp1 + eyhx1) * v1, -(kp3 - eyhx1) * v1);
        // Bottom: V=(-hx,-hy), d=(+2hx,0):  1/s_j = -w_j
        dts += edgeA((km0 + eyhx0) * w0, -(km2 - eyhx0) * w0,
                     (km1 + eyhx1) * w1, -(km3 - eyhx1) * w1);
        // Right:  V=(+hx,-hy), d=(0,+2hy):  1/s_j = +v_j
        dts += edgeA(-(km0 - eyhx0) * v0, (km2 + eyhx0) * v0,
                     -(km1 - eyhx1) * v1, (km3 + eyhx1) * v1);

        // Every A-edge cross-term = cross(V, d) = 2*hx*hy.
        acc = fmaf(dts, 2.0f * hx * hy, acc);
    }

    const float inter_vol = 0.5f * fabsf(acc) * zo;
    const float iou = __fdividef(inter_vol, s - inter_vol);

    float lnum = act ? fabsf(ip - (2.0f * iou - 1.0f)) : 0.0f;
    int lcnt = __popc(ball);

    // ---- block reduction ----
#pragma unroll
    for (int off = 16; off > 0; off >>= 1)
        lnum += __shfl_down_sync(0xffffffffu, lnum, off);
    if (lane == 0) { s_red[w] = lnum; s_cnt[w] = lcnt; }
    __syncthreads();
    if (w == 0) {
        lnum = (lane < NW) ? s_red[lane] : 0.0f;
        lcnt = (lane < NW) ? s_cnt[lane] : 0;
#pragma unroll
        for (int off = NW / 2; off > 0; off >>= 1) {
            lnum += __shfl_down_sync(0xffffffffu, lnum, off);
            lcnt += __shfl_down_sync(0xffffffffu, lcnt, off);
        }
        // ---- last-block finalize (threadfence reduction pattern) ----
        if (lane == 0) {
            atomicAdd(&g_num, lnum);
            atomicAdd(&g_cnt, lcnt);
            __threadfence();
            unsigned int old = atomicAdd(&g_done, 1u);
            if (old == NBLK - 1) {
                __threadfence();
                float num = *((volatile float*)&g_num);
                int cnt = *((volatile int*)&g_cnt);
                out[0] = num / ((float)cnt + 1e-4f);
                g_num = 0.0f;       // reset for next graph replay
                g_cnt = 0;
                g_done = 0u;
            }
        }
    }
}

extern "C" void kernel_launch(void* const* d_in, const int* in_sizes, int n_in,
                              void* d_out, int out_size) {
    const float* iou_pred = (const float*)d_in[0];
    const int* mask = (const int*)d_in[1];
    // d_in[2] = ind (unused)
    const float* box_pred = (const float*)d_in[3];
    const float* box_gt = (const float*)d_in[4];
    float* out = (float*)d_out;

    iou_k<<<NBLK, TPB>>>(iou_pred, mask, box_pred, box_gt, out);
}